// round 10
// baseline (speedup 1.0000x reference)
#include <cuda_runtime.h>
#include <math.h>

// QLSTM: seq=2048, batch=64, in=512, hid=512
// Persistent fp32 kernel, 128 CTAs (1/SM), grid barrier per step.
// R7: packed fma.rn.f32x2 inner loop (A pre-duplicated in smem),
//     barrier hidden behind x-projection chunks, 1 sync per chunk.

#define SEQ    2048
#define BATCH  64
#define HID    512
#define KTOT   1024
#define NCTA   128
#define ROWS   32
#define GCOLS  32
#define KC     128
#define NCHUNK 8

// float offsets in dynamic smem
#define WS_OFF   0            // [1024][32] weights            = 32768 floats
#define ASP_OFF  32768        // 2 x [128 k][32 row] dup-f32x2 = 16384 floats
#define SG_OFF   (32768+16384)// [32][33] gate staging         =  1056 floats
#define BS_OFF   (SG_OFF+1056)// [32] bias
#define SMEM_FLOATS (BS_OFF + 32)

__device__ __align__(16) float g_hx[2][BATCH * HID];
__device__ int g_count;

__global__ void qlstm_init_kernel() {
    int i = blockIdx.x * blockDim.x + threadIdx.x;
    if (i < 2 * BATCH * HID) ((float*)g_hx)[i] = 0.0f;
    if (i == 0) g_count = 0;
}

__global__ __launch_bounds__(256, 1) void qlstm_kernel(
    const float* __restrict__ x,
    const float* __restrict__ Wf, const float* __restrict__ bf,
    const float* __restrict__ Wi, const float* __restrict__ bi,
    const float* __restrict__ Wg, const float* __restrict__ bg,
    const float* __restrict__ Wo, const float* __restrict__ bo,
    float* __restrict__ out)
{
    extern __shared__ float sm[];
    float*  Ws  = sm + WS_OFF;
    float2* Asp = reinterpret_cast<float2*>(sm + ASP_OFF); // element (k,row) dup pair
    float*  Sg  = sm + SG_OFF;
    float*  bs  = sm + BS_OFF;

    const unsigned smem_u = (unsigned)__cvta_generic_to_shared(sm);
    const unsigned ws_u   = smem_u + WS_OFF * 4u;
    const unsigned asp_u  = smem_u + ASP_OFF * 4u;

    const int tid = threadIdx.x;
    const int cg  = blockIdx.x;            // 0..63 hidden col group
    const int bh  = blockIdx.y;            // 0..1 batch half
    const int rb0 = bh * ROWS;

    // ---- one-time weight + bias slice load ----
    for (int idx = tid; idx < KTOT * GCOLS; idx += 256) {
        int k = idx >> 5, c = idx & 31;
        int g = c >> 3, j = cg * 8 + (c & 7);
        const float* w = (g == 0) ? Wf : (g == 1) ? Wi : (g == 2) ? Wg : Wo;
        Ws[idx] = w[k * HID + j];
    }
    if (tid < GCOLS) {
        int g = tid >> 3, j = cg * 8 + (tid & 7);
        const float* bb = (g == 0) ? bf : (g == 1) ? bi : (g == 2) ? bg : bo;
        bs[tid] = bb[tid & 7 ? j : j];  // bb[j]
        bs[tid] = bb[j];
    }
    __syncthreads();

    const int ty = tid >> 4, tx = tid & 15;   // GEMM: rows (2ty,2ty+1), cols (2tx,2tx+1)
    const int bl = tid >> 3, jj = tid & 7;    // epilogue cell
    const int b  = rb0 + bl;
    const int j  = cg * 8 + jj;

    // loader mapping: each thread covers row = tid>>3, kq = (tid&7)+8s
    const int lrow = tid >> 3;
    const int lkq0 = tid & 7;

    float creg = 0.0f;

    for (int t = 0; t < SEQ; t++) {
        const float4* xbase = reinterpret_cast<const float4*>(x) +
                              (size_t)(t * BATCH + rb0) * (HID / 4);
        const float4* hbase = reinterpret_cast<const float4*>(g_hx[t & 1]) +
                              (size_t)rb0 * (HID / 4);

        auto load_chunk = [&](int c, float4 r[4]) {
            if (c < 4) {
                #pragma unroll
                for (int s = 0; s < 4; s++)
                    r[s] = __ldg(xbase + lrow * (HID / 4) + c * 32 + (lkq0 + 8 * s));
            } else {
                #pragma unroll
                for (int s = 0; s < 4; s++)
                    r[s] = __ldcg(hbase + lrow * (HID / 4) + (c - 4) * 32 + (lkq0 + 8 * s));
            }
        };
        // duplicate-store with pair-preserving XOR swizzle
        auto store_chunk = [&](int buf, const float4 r[4]) {
            float2* dst = Asp + buf * (KC * ROWS);
            #pragma unroll
            for (int s = 0; s < 4; s++) {
                int kq = lkq0 + 8 * s;
                int rowx = lrow ^ ((kq & 15) << 1);
                float2* p = dst + (4 * kq) * 32 + rowx;
                p[0 * 32] = make_float2(r[s].x, r[s].x);
                p[1 * 32] = make_float2(r[s].y, r[s].y);
                p[2 * 32] = make_float2(r[s].z, r[s].z);
                p[3 * 32] = make_float2(r[s].w, r[s].w);
            }
        };

        unsigned long long acc0 = 0ull, acc1 = 0ull;   // packed (col 2tx, 2tx+1) x rows 2ty,2ty+1

        // prologue: chunk 0 (x) into buf 0
        {
            float4 r[4];
            load_chunk(0, r);
            store_chunk(0, r);
        }
        __syncthreads();

        #pragma unroll 1
        for (int c = 0; c < NCHUNK; c++) {
            // hide grid barrier behind x-chunks: wait before issuing first h load
            if (c == 3) {
                if (tid == 0) {
                    int target = NCTA * t;
                    while (*(volatile int*)&g_count < target) { }
                    __threadfence();
                }
                __syncthreads();
            }

            float4 rn[4];
            if (c + 1 < NCHUNK) load_chunk(c + 1, rn);

            // ---- packed-f32x2 GEMM on buf[c&1] ----
            const unsigned abuf  = asp_u + (unsigned)((c & 1) * (KC * ROWS * 8));
            const unsigned wbase = ws_u + (unsigned)((c * KC * GCOLS + 2 * tx) * 4);
            #pragma unroll 8
            for (int k4 = 0; k4 < KC / 4; k4++) {
                unsigned rowx = (unsigned)((2 * ty) ^ ((k4 & 15) << 1));
                unsigned aa = abuf + (unsigned)(k4 * 1024) + rowx * 8u;
                unsigned wa = wbase + (unsigned)(k4 * 512);
                unsigned long long pa0, pa1, pb0, pb1, pc0, pc1, pd0, pd1;
                unsigned long long w0, w1, w2, w3;
                asm volatile("ld.shared.v2.b64 {%0,%1},[%2];" : "=l"(pa0), "=l"(pa1) : "r"(aa));
                asm volatile("ld.shared.v2.b64 {%0,%1},[%2];" : "=l"(pb0), "=l"(pb1) : "r"(aa + 256u));
                asm volatile("ld.shared.v2.b64 {%0,%1},[%2];" : "=l"(pc0), "=l"(pc1) : "r"(aa + 512u));
                asm volatile("ld.shared.v2.b64 {%0,%1},[%2];" : "=l"(pd0), "=l"(pd1) : "r"(aa + 768u));
                asm volatile("ld.shared.b64 %0,[%1];" : "=l"(w0) : "r"(wa));
                asm volatile("ld.shared.b64 %0,[%1];" : "=l"(w1) : "r"(wa + 128u));
                asm volatile("ld.shared.b64 %0,[%1];" : "=l"(w2) : "r"(wa + 256u));
                asm volatile("ld.shared.b64 %0,[%1];" : "=l"(w3) : "r"(wa + 384u));
                asm volatile("fma.rn.f32x2 %0,%1,%2,%0;" : "+l"(acc0) : "l"(pa0), "l"(w0));
                asm volatile("fma.rn.f32x2 %0,%1,%2,%0;" : "+l"(acc1) : "l"(pa1), "l"(w0));
                asm volatile("fma.rn.f32x2 %0,%1,%2,%0;" : "+l"(acc0) : "l"(pb0), "l"(w1));
                asm volatile("fma.rn.f32x2 %0,%1,%2,%0;" : "+l"(acc1) : "l"(pb1), "l"(w1));
                asm volatile("fma.rn.f32x2 %0,%1,%2,%0;" : "+l"(acc0) : "l"(pc0), "l"(w2));
                asm volatile("fma.rn.f32x2 %0,%1,%2,%0;" : "+l"(acc1) : "l"(pc1), "l"(w2));
                asm volatile("fma.rn.f32x2 %0,%1,%2,%0;" : "+l"(acc0) : "l"(pd0), "l"(w3));
                asm volatile("fma.rn.f32x2 %0,%1,%2,%0;" : "+l"(acc1) : "l"(pd1), "l"(w3));
            }

            if (c + 1 < NCHUNK) store_chunk((c + 1) & 1, rn);
            __syncthreads();
        }

        // unpack: acc0 = (row 2ty: col 2tx lo, col 2tx+1 hi); acc1 = row 2ty+1
        float acc00 = __uint_as_float((unsigned)(acc0));
        float acc01 = __uint_as_float((unsigned)(acc0 >> 32));
        float acc10 = __uint_as_float((unsigned)(acc1));
        float acc11 = __uint_as_float((unsigned)(acc1 >> 32));

        Sg[(2 * tx)     * 33 + 2 * ty]     = acc00;
        Sg[(2 * tx + 1) * 33 + 2 * ty]     = acc01;
        Sg[(2 * tx)     * 33 + 2 * ty + 1] = acc10;
        Sg[(2 * tx + 1) * 33 + 2 * ty + 1] = acc11;
        __syncthreads();

        float pf = Sg[(jj)      * 33 + bl] + bs[jj];
        float pi = Sg[(8 + jj)  * 33 + bl] + bs[8 + jj];
        float pg = Sg[(16 + jj) * 33 + bl] + bs[16 + jj];
        float po = Sg[(24 + jj) * 33 + bl] + bs[24 + jj];
        float fgate = 1.0f / (1.0f + expf(-pf));
        float igate = 1.0f / (1.0f + expf(-pi));
        float ggate = tanhf(pg);
        float ogate = 1.0f / (1.0f + expf(-po));
        creg = fgate * creg + igate * ggate;
        float h = ogate * tanhf(creg);

        out[((size_t)t * BATCH + b) * HID + j] = h;
        __stcg(&g_hx[(t + 1) & 1][b * HID + j], h);
        if (t == SEQ - 1) {
            size_t base = (size_t)SEQ * BATCH * HID;
            out[base + b * HID + j] = h;                   // final hx
            out[base + BATCH * HID + b * HID + j] = creg;  // final cx
        }

        // arrive (wait is at next step's c==3)
        __threadfence();
        __syncthreads();
        if (tid == 0) atomicAdd(&g_count, 1);
    }
}

extern "C" void kernel_launch(void* const* d_in, const int* in_sizes, int n_in,
                              void* d_out, int out_size) {
    (void)in_sizes; (void)n_in; (void)out_size;
    const float* x  = (const float*)d_in[0];
    const float* Wf = (const float*)d_in[1];
    const float* bf = (const float*)d_in[2];
    const float* Wi = (const float*)d_in[3];
    const float* bi = (const float*)d_in[4];
    const float* Wg = (const float*)d_in[5];
    const float* bg = (const float*)d_in[6];
    const float* Wo = (const float*)d_in[7];
    const float* bo = (const float*)d_in[8];
    float* out = (float*)d_out;

    qlstm_init_kernel<<<256, 256>>>();

    size_t smem_bytes = (size_t)SMEM_FLOATS * sizeof(float);
    cudaFuncSetAttribute(qlstm_kernel,
                         cudaFuncAttributeMaxDynamicSharedMemorySize,
                         (int)smem_bytes);
    dim3 grid(64, 2);
    qlstm_kernel<<<grid, 256, smem_bytes>>>(x, Wf, bf, Wi, bi, Wg, bg, Wo, bo, out);
}

// round 13
// speedup vs baseline: 1.7136x; 1.7136x over previous
#include <cuda_runtime.h>
#include <cuda_bf16.h>
#include <math.h>
#include <stdint.h>

// QLSTM seq=2048 batch=64 in=512 hid=512
// mma.sync m16n8k16 bf16 3-term split GEMM, 64 persistent CTAs,
// grid barrier per step. Works on compute_103 (no 'a' features).

#define SEQ    2048
#define BATCH  64
#define HID    512
#define KTOT   1024
#define NCTA   64
#define KC     128

// smem byte offsets
#define BS_OFF     0                         // 32 bias floats (128 B)
#define WH_OFF     1024                      // [32 n][1024 k] bf16 = 65536
#define WL_OFF     (WH_OFF + 65536)
#define A_OFF      (WL_OFF + 65536)          // 2 bufs x (hi 16384 + lo 16384)
#define SMEM_BYTES (A_OFF + 2 * 32768)       // 197632

__device__ uint32_t g_xsplit[(size_t)SEQ * BATCH * HID];  // bf16 hi | lo<<16
__device__ uint32_t g_hxs[2][BATCH * HID];
__device__ int g_count;

__device__ __forceinline__ uint32_t packsplit(float a) {
    __nv_bfloat16 h = __float2bfloat16(a);
    float hf = __bfloat162float(h);
    __nv_bfloat16 l = __float2bfloat16(a - hf);
    return (uint32_t)__bfloat16_as_ushort(h) |
           ((uint32_t)__bfloat16_as_ushort(l) << 16);
}

__global__ void qlstm_init_kernel() {
    int i = blockIdx.x * blockDim.x + threadIdx.x;
    if (i < 2 * BATCH * HID) ((uint32_t*)g_hxs)[i] = 0u;
    if (i == 0) g_count = 0;
}

__global__ void qlstm_xsplit_kernel(const float* __restrict__ x) {
    int i = blockIdx.x * blockDim.x + threadIdx.x;
    int stride = gridDim.x * blockDim.x;
    int total = SEQ * BATCH * HID / 4;
    const float4* xv = (const float4*)x;
    uint4* ov = (uint4*)g_xsplit;
    for (; i < total; i += stride) {
        float4 v = xv[i];
        uint4 o;
        o.x = packsplit(v.x); o.y = packsplit(v.y);
        o.z = packsplit(v.z); o.w = packsplit(v.w);
        ov[i] = o;
    }
}

#define LDSM4(r0, r1, r2, r3, a) \
    asm volatile("ldmatrix.sync.aligned.m8n8.x4.shared.b16 {%0,%1,%2,%3}, [%4];" \
                 : "=r"(r0), "=r"(r1), "=r"(r2), "=r"(r3) : "r"(a))

#define MMA(acc, i0, a0, a1, a2, a3, b0, b1) \
    asm volatile("mma.sync.aligned.m16n8k16.row.col.f32.bf16.bf16.f32 " \
                 "{%0,%1,%2,%3}, {%4,%5,%6,%7}, {%8,%9}, {%0,%1,%2,%3};" \
                 : "+f"(acc[i0]), "+f"(acc[i0 + 1]), "+f"(acc[i0 + 2]), "+f"(acc[i0 + 3]) \
                 : "r"(a0), "r"(a1), "r"(a2), "r"(a3), "r"(b0), "r"(b1))

__global__ __launch_bounds__(256, 1) void qlstm_mma_kernel(
    const float* __restrict__ p_Wf, const float* __restrict__ p_bf,
    const float* __restrict__ p_Wi, const float* __restrict__ p_bi,
    const float* __restrict__ p_Wg, const float* __restrict__ p_bg,
    const float* __restrict__ p_Wo, const float* __restrict__ p_bo,
    float* __restrict__ out)
{
    extern __shared__ char smem[];
    const uint32_t smem_u = (uint32_t)__cvta_generic_to_shared(smem);
    const int tid = threadIdx.x, wid = tid >> 5, lane = tid & 31;
    const int cg = blockIdx.x;                      // 0..63: 8 hidden js

    // ---- one-time: W slice -> bf16 hi/lo swizzled [n][k] tiles + bias ----
    // col n = jj*4 + gate; swizzle: byte ^ ((n&7)<<4)
    for (int idx = tid; idx < 32 * KTOT; idx += 256) {
        int n = idx & 31, k = idx >> 5;
        int g = n & 3, j = cg * 8 + (n >> 2);
        const float* w = (g == 0) ? p_Wf : (g == 1) ? p_Wi : (g == 2) ? p_Wg : p_Wo;
        float v = w[k * HID + j];
        __nv_bfloat16 hb = __float2bfloat16(v);
        __nv_bfloat16 lb = __float2bfloat16(v - __bfloat162float(hb));
        int byte = n * 2048 + k * 2;
        int sw = byte ^ ((n & 7) << 4);
        *(__nv_bfloat16*)(smem + WH_OFF + sw) = hb;
        *(__nv_bfloat16*)(smem + WL_OFF + sw) = lb;
    }
    if (tid < 32) {
        int g = tid & 3, j = cg * 8 + (tid >> 2);
        const float* bb = (g == 0) ? p_bf : (g == 1) ? p_bi : (g == 2) ? p_bg : p_bo;
        *(float*)(smem + BS_OFF + tid * 4) = bb[j];
    }
    __syncthreads();

    // ---- per-warp/lane constants ----
    const int m0 = (wid & 3) * 16;                  // batch-row base of m16 tile
    const int n0 = (wid >> 2) * 16;                 // col base of n16 tile

    // A ldmatrix: lanes 0-15 rows, lanes 16-31 k-half 1
    const int arow = m0 + (lane & 15);
    const uint32_t a_rowterm = (uint32_t)arow * 256u;
    const uint32_t a_kxor = (uint32_t)(((lane >> 4) * 16) ^ ((arow & 7) << 4));
    // B ldmatrix: [lanes 0-7: n0..n0+7 kh0][8-15: kh1][16-23: n0+8.. kh0][24-31: kh1]
    const int bn = n0 + (lane >> 4) * 8 + (lane & 7);
    const uint32_t b_nterm = (uint32_t)bn * 2048u;
    const uint32_t b_kxor = (uint32_t)((((lane >> 3) & 1) * 16) ^ ((bn & 7) << 4));

    // loader mapping: row = tid>>2 (0..63), uint4 col = (tid&3) + 4s
    const int lrow = tid >> 2;
    const int lq = tid & 3;
    const uint32_t sts_rowterm = (uint32_t)lrow * 256u;
    const uint32_t sts_xor = (uint32_t)((lrow & 7) << 4);

    // epilogue mapping
    const int brow = m0 + (lane >> 2) + ((lane & 1) * 8);
    const int jjl = (n0 >> 2) + ((lane & 3) >> 1);  // local jj (0..7), cells jjl, jjl+2
    const float* bsf = (const float*)(smem + BS_OFF);
    const float bfA = bsf[jjl * 4 + 0], biA = bsf[jjl * 4 + 1];
    const float bgA = bsf[jjl * 4 + 2], boA = bsf[jjl * 4 + 3];
    const float bfB = bsf[(jjl + 2) * 4 + 0], biB = bsf[(jjl + 2) * 4 + 1];
    const float bgB = bsf[(jjl + 2) * 4 + 2], boB = bsf[(jjl + 2) * 4 + 3];

    float cA = 0.f, cB = 0.f;
    uint4 r[8];

    for (int t = 0; t < SEQ; t++) {
        // ---- prologue: chunk 0 (x) ----
        {
            const uint4* src = (const uint4*)&g_xsplit[((size_t)t * BATCH + lrow) * HID];
            #pragma unroll
            for (int s = 0; s < 8; s++) r[s] = __ldg(src + lq + 4 * s);
        }
        // STS chunk 0 into buf 0 (split hi/lo, swizzled)
        #pragma unroll
        for (int s = 0; s < 8; s++) {
            uint32_t byte = sts_rowterm + (uint32_t)(8 * (lq + 4 * s));
            uint32_t sw = byte ^ sts_xor;
            uint32_t hi0 = __byte_perm(r[s].x, r[s].y, 0x5410);
            uint32_t hi1 = __byte_perm(r[s].z, r[s].w, 0x5410);
            uint32_t lo0 = __byte_perm(r[s].x, r[s].y, 0x7632);
            uint32_t lo1 = __byte_perm(r[s].z, r[s].w, 0x7632);
            asm volatile("st.shared.v2.b32 [%0], {%1,%2};"
                         :: "r"(smem_u + A_OFF + sw), "r"(hi0), "r"(hi1));
            asm volatile("st.shared.v2.b32 [%0], {%1,%2};"
                         :: "r"(smem_u + A_OFF + 16384 + sw), "r"(lo0), "r"(lo1));
        }
        __syncthreads();

        float acc[8] = {0.f, 0.f, 0.f, 0.f, 0.f, 0.f, 0.f, 0.f};

        #pragma unroll
        for (int c = 0; c < 8; c++) {
            // prefetch next chunk (grid-barrier before first h chunk)
            if (c < 7) {
                int cn = c + 1;
                if (cn == 4) {
                    if (tid == 0) {
                        while (*(volatile int*)&g_count < NCTA * t) { }
                        __threadfence();
                    }
                    __syncthreads();
                }
                if (cn < 4) {
                    const uint4* src = (const uint4*)
                        &g_xsplit[((size_t)t * BATCH + lrow) * HID + cn * KC];
                    #pragma unroll
                    for (int s = 0; s < 8; s++) r[s] = __ldg(src + lq + 4 * s);
                } else {
                    const uint4* src = (const uint4*)
                        &g_hxs[t & 1][lrow * HID + (cn - 4) * KC];
                    #pragma unroll
                    for (int s = 0; s < 8; s++) r[s] = __ldcg(src + lq + 4 * s);
                }
            }

            // ---- MMA over buf[c&1]: 3-term split ----
            const uint32_t abase = smem_u + A_OFF + (uint32_t)((c & 1) * 32768) + a_rowterm;
            const uint32_t bbase = smem_u + WH_OFF + b_nterm;
            const uint32_t bkc = (uint32_t)(c * 256);
            #pragma unroll
            for (int ks = 0; ks < 8; ks++) {
                uint32_t aaddr = abase + (((uint32_t)(ks * 32)) ^ a_kxor);
                uint32_t baddr = bbase + ((bkc + (uint32_t)(ks * 32)) ^ b_kxor);
                uint32_t ah0, ah1, ah2, ah3, al0, al1, al2, al3;
                uint32_t bh0, bh1, bh2, bh3, bl0, bl1, bl2, bl3;
                LDSM4(ah0, ah1, ah2, ah3, aaddr);
                LDSM4(al0, al1, al2, al3, aaddr + 16384u);
                LDSM4(bh0, bh1, bh2, bh3, baddr);
                LDSM4(bl0, bl1, bl2, bl3, baddr + 65536u);
                MMA(acc, 0, ah0, ah1, ah2, ah3, bh0, bh1);
                MMA(acc, 4, ah0, ah1, ah2, ah3, bh2, bh3);
                MMA(acc, 0, al0, al1, al2, al3, bh0, bh1);
                MMA(acc, 4, al0, al1, al2, al3, bh2, bh3);
                MMA(acc, 0, ah0, ah1, ah2, ah3, bl0, bl1);
                MMA(acc, 4, ah0, ah1, ah2, ah3, bl2, bl3);
            }

            // STS next chunk into buf[(c+1)&1]
            if (c < 7) {
                uint32_t bufoff = (uint32_t)(((c + 1) & 1) * 32768);
                #pragma unroll
                for (int s = 0; s < 8; s++) {
                    uint32_t byte = sts_rowterm + (uint32_t)(8 * (lq + 4 * s));
                    uint32_t sw = byte ^ sts_xor;
                    uint32_t hi0 = __byte_perm(r[s].x, r[s].y, 0x5410);
                    uint32_t hi1 = __byte_perm(r[s].z, r[s].w, 0x5410);
                    uint32_t lo0 = __byte_perm(r[s].x, r[s].y, 0x7632);
                    uint32_t lo1 = __byte_perm(r[s].z, r[s].w, 0x7632);
                    asm volatile("st.shared.v2.b32 [%0], {%1,%2};"
                                 :: "r"(smem_u + A_OFF + bufoff + sw), "r"(hi0), "r"(hi1));
                    asm volatile("st.shared.v2.b32 [%0], {%1,%2};"
                                 :: "r"(smem_u + A_OFF + bufoff + 16384u + sw), "r"(lo0), "r"(lo1));
                }
                __syncthreads();
            }
        }

        // ---- epilogue: exchange halves, cell update ----
        // even lane (lane&1==0) -> row m0+(lane>>2): has f,i; partner has g,o
        // odd lane -> row m0+8+(lane>>2): has g,o; partner has f,i
        float d0 = __shfl_xor_sync(0xffffffffu, acc[0], 1);
        float d1 = __shfl_xor_sync(0xffffffffu, acc[1], 1);
        float d2 = __shfl_xor_sync(0xffffffffu, acc[2], 1);
        float d3 = __shfl_xor_sync(0xffffffffu, acc[3], 1);
        float d4 = __shfl_xor_sync(0xffffffffu, acc[4], 1);
        float d5 = __shfl_xor_sync(0xffffffffu, acc[5], 1);
        float d6 = __shfl_xor_sync(0xffffffffu, acc[6], 1);
        float d7 = __shfl_xor_sync(0xffffffffu, acc[7], 1);
        float pfA, piA, pgA, poA, pfB, piB, pgB, poB;
        if ((lane & 1) == 0) {
            pfA = acc[0]; piA = acc[1]; pgA = d0; poA = d1;
            pfB = acc[4]; piB = acc[5]; pgB = d4; poB = d5;
        } else {
            pfA = d2; piA = d3; pgA = acc[2]; poA = acc[3];
            pfB = d6; piB = d7; pgB = acc[6]; poB = acc[7];
        }
        pfA += bfA; piA += biA; pgA += bgA; poA += boA;
        pfB += bfB; piB += biB; pgB += bgB; poB += boB;

        float fA = 1.0f / (1.0f + __expf(-pfA));
        float iA = 1.0f / (1.0f + __expf(-piA));
        float gA = tanhf(pgA);
        float oA = 1.0f / (1.0f + __expf(-poA));
        cA = fA * cA + iA * gA;
        float hA = oA * tanhf(cA);

        float fB = 1.0f / (1.0f + __expf(-pfB));
        float iB = 1.0f / (1.0f + __expf(-piB));
        float gB = tanhf(pgB);
        float oB = 1.0f / (1.0f + __expf(-poB));
        cB = fB * cB + iB * gB;
        float hB = oB * tanhf(cB);

        int jA = cg * 8 + jjl, jB = jA + 2;
        size_t obase = ((size_t)t * BATCH + brow) * HID;
        out[obase + jA] = hA;
        out[obase + jB] = hB;
        __stcg(&g_hxs[(t + 1) & 1][brow * HID + jA], packsplit(hA));
        __stcg(&g_hxs[(t + 1) & 1][brow * HID + jB], packsplit(hB));
        if (t == SEQ - 1) {
            size_t base = (size_t)SEQ * BATCH * HID;
            out[base + brow * HID + jA] = hA;
            out[base + brow * HID + jB] = hB;
            out[base + BATCH * HID + brow * HID + jA] = cA;
            out[base + BATCH * HID + brow * HID + jB] = cB;
        }

        __threadfence();
        __syncthreads();
        if (tid == 0) atomicAdd(&g_count, 1);
    }
}

extern "C" void kernel_launch(void* const* d_in, const int* in_sizes, int n_in,
                              void* d_out, int out_size) {
    (void)in_sizes; (void)n_in; (void)out_size;
    const float* x  = (const float*)d_in[0];
    const float* Wf = (const float*)d_in[1];
    const float* bf = (const float*)d_in[2];
    const float* Wi = (const float*)d_in[3];
    const float* bi = (const float*)d_in[4];
    const float* Wg = (const float*)d_in[5];
    const float* bg = (const float*)d_in[6];
    const float* Wo = (const float*)d_in[7];
    const float* bo = (const float*)d_in[8];
    float* out = (float*)d_out;

    qlstm_init_kernel<<<256, 256>>>();
    qlstm_xsplit_kernel<<<2048, 256>>>(x);

    cudaFuncSetAttribute(qlstm_mma_kernel,
                         cudaFuncAttributeMaxDynamicSharedMemorySize, SMEM_BYTES);
    qlstm_mma_kernel<<<NCTA, 256, SMEM_BYTES>>>(Wf, bf, Wi, bi, Wg, bg, Wo, bo, out);
}